// round 9
// baseline (speedup 1.0000x reference)
#include <cuda_runtime.h>
#include <cstdint>

#define BH    8
#define DK    64
#define DVV   64
#define NSEQ  2048
#define MF    128
#define CHUNK 128
#define NC    16
#define VP    72          // DV padded: col 64 = ones (z / norm), 65..71 = 0

#define PHI_SCALE 0.08838834764831845f   // 1/sqrt(128)

// Per-(head,chunk) fused chunk state [S | z | pad] : [m][VP], fp32
// (kB converts to exclusive prefix over chunks)
__device__ float g_S[BH * NC * MF * VP];     // 4.7 MB

// ---------------------------------------------------------------------------
__device__ __forceinline__ uint32_t f2tf(float f) {
    uint32_t r; asm("cvt.rna.tf32.f32 %0, %1;" : "=r"(r) : "f"(f)); return r;
}
__device__ __forceinline__ void mma8(float* d, const uint32_t* A, const uint32_t* B) {
    asm volatile("mma.sync.aligned.m16n8k8.row.col.f32.tf32.tf32.f32 "
                 "{%0,%1,%2,%3}, {%4,%5,%6,%7}, {%8,%9}, {%0,%1,%2,%3};"
                 : "+f"(d[0]), "+f"(d[1]), "+f"(d[2]), "+f"(d[3])
                 : "r"(A[0]), "r"(A[1]), "r"(A[2]), "r"(A[3]), "r"(B[0]), "r"(B[1]));
}

// Strides (words): A-operand tiles ≡4 (mod 32), B-operand tiles ≡8 (mod 32).
#define STR_KQ  68
#define STR_F   136
#define STR_PKT 136
#define STR_PQ  132
#define STR_SC  132
#define STR_V   72
#define STR_ST  72
#define STR_PK  136

// ===========================================================================
// Kernel A (512 thr, measured 18.5us in R8): phi_k = relu(K F^T)*s ;
// chunk state [S|z] = phiK^T [V;1]
// ===========================================================================
#define A_F   0        // 64x136  = 8704
#define A_K   8704     // 128x68  = 8704
#define A_V   17408    // 128x72  = 9216
#define A_PKT 26624    // 128x136 = 17408
#define A_SMW 44032
#define A_SMB (A_SMW * 4)

__global__ void __launch_bounds__(512, 1)
kA(const float* __restrict__ keys, const float* __restrict__ values,
   const float* __restrict__ feat)
{
    extern __shared__ uint32_t sm[];
    const int t = threadIdx.x, w = t >> 5, lane = t & 31;
    const int g = lane >> 2, tg = lane & 3;
    const int c = blockIdx.x, h = blockIdx.y, nbase = c * CHUNK;
    const size_t hc = (size_t)(h * NC + c);

    // ---- stage F, K, V+ ----
    for (int idx = t; idx < MF * 16; idx += 512) {
        int m = idx >> 4, d4 = (idx & 15) << 2;
        float4 x = *(const float4*)&feat[m * DK + d4];
        sm[A_F + (d4 + 0) * STR_F + m] = f2tf(x.x);
        sm[A_F + (d4 + 1) * STR_F + m] = f2tf(x.y);
        sm[A_F + (d4 + 2) * STR_F + m] = f2tf(x.z);
        sm[A_F + (d4 + 3) * STR_F + m] = f2tf(x.w);
    }
    for (int idx = t; idx < DK * 32; idx += 512) {
        int d = idx >> 5, i4 = (idx & 31) << 2;
        float4 x = *(const float4*)&keys[(h * DK + d) * NSEQ + nbase + i4];
        sm[A_K + (i4 + 0) * STR_KQ + d] = f2tf(x.x);
        sm[A_K + (i4 + 1) * STR_KQ + d] = f2tf(x.y);
        sm[A_K + (i4 + 2) * STR_KQ + d] = f2tf(x.z);
        sm[A_K + (i4 + 3) * STR_KQ + d] = f2tf(x.w);
    }
    for (int idx = t; idx < DVV * 32; idx += 512) {
        int v = idx >> 5, j4 = (idx & 31) << 2;
        float4 x = *(const float4*)&values[(h * DVV + v) * NSEQ + nbase + j4];
        sm[A_V + (j4 + 0) * STR_V + v] = f2tf(x.x);
        sm[A_V + (j4 + 1) * STR_V + v] = f2tf(x.y);
        sm[A_V + (j4 + 2) * STR_V + v] = f2tf(x.z);
        sm[A_V + (j4 + 3) * STR_V + v] = f2tf(x.w);
    }
    for (int idx = t; idx < CHUNK * 8; idx += 512) {
        int j = idx >> 3, v = 64 + (idx & 7);
        sm[A_V + j * STR_V + v] = (v == 64) ? 0x3F800000u : 0u;
    }
    __syncthreads();

    const int wm0 = (w & 3) * 32, wn0 = (w >> 2) * 32;

    // ---- GEMM1: phi_k [i][m], warp tile 32x32, K=64 ----
    {
        float D[2][4][4] = {};
        #pragma unroll
        for (int kk = 0; kk < 64; kk += 8) {
            uint32_t A[2][4], B[4][2];
            #pragma unroll
            for (int ms = 0; ms < 2; ms++) {
                int r0 = wm0 + ms * 16 + g;
                A[ms][0] = sm[A_K + r0 * STR_KQ + kk + tg];
                A[ms][1] = sm[A_K + (r0 + 8) * STR_KQ + kk + tg];
                A[ms][2] = sm[A_K + r0 * STR_KQ + kk + tg + 4];
                A[ms][3] = sm[A_K + (r0 + 8) * STR_KQ + kk + tg + 4];
            }
            #pragma unroll
            for (int ns = 0; ns < 4; ns++) {
                B[ns][0] = sm[A_F + (kk + tg) * STR_F + wn0 + ns * 8 + g];
                B[ns][1] = sm[A_F + (kk + tg + 4) * STR_F + wn0 + ns * 8 + g];
            }
            #pragma unroll
            for (int ms = 0; ms < 2; ms++)
                #pragma unroll
                for (int ns = 0; ns < 4; ns++) mma8(D[ms][ns], A[ms], B[ns]);
        }
        // epilogue: relu*scale -> phiK^T [m][i]
        #pragma unroll
        for (int ms = 0; ms < 2; ms++)
            #pragma unroll
            for (int ns = 0; ns < 4; ns++)
                #pragma unroll
                for (int e = 0; e < 4; e++) {
                    int ri = wm0 + ms * 16 + g + ((e >> 1) << 3);
                    int cm = wn0 + ns * 8 + tg * 2 + (e & 1);
                    sm[A_PKT + cm * STR_PKT + ri] =
                        f2tf(fmaxf(D[ms][ns][e], 0.f) * PHI_SCALE);
                }
    }
    __syncthreads();

    // ---- GEMM2: [S|z] = phiK^T · [V;1]; 8 M-tiles x 2 N-halves ----
    {
        const int m0 = (w >> 1) * 16, half = w & 1;
        const int nsB = half ? 5 : 0, nsC = half ? 4 : 5;
        float D[5][4] = {};
        #pragma unroll
        for (int kk = 0; kk < CHUNK; kk += 8) {
            uint32_t A[4];
            A[0] = sm[A_PKT + (m0 + g) * STR_PKT + kk + tg];
            A[1] = sm[A_PKT + (m0 + g + 8) * STR_PKT + kk + tg];
            A[2] = sm[A_PKT + (m0 + g) * STR_PKT + kk + tg + 4];
            A[3] = sm[A_PKT + (m0 + g + 8) * STR_PKT + kk + tg + 4];
            #pragma unroll
            for (int s = 0; s < 5; s++) {
                if (s >= nsC) break;
                int ns = nsB + s;
                uint32_t B[2];
                B[0] = sm[A_V + (kk + tg) * STR_V + ns * 8 + g];
                B[1] = sm[A_V + (kk + tg + 4) * STR_V + ns * 8 + g];
                mma8(D[s], A, B);
            }
        }
        float* Sg = g_S + hc * MF * VP;
        #pragma unroll
        for (int s = 0; s < 5; s++) {
            if (s >= nsC) break;
            #pragma unroll
            for (int e = 0; e < 4; e++) {
                int row = m0 + g + ((e >> 1) << 3);
                int col = (nsB + s) * 8 + tg * 2 + (e & 1);
                Sg[row * VP + col] = D[s][e];
            }
        }
    }
}

// ===========================================================================
// Kernel B: exclusive prefix over chunks of g_S (elementwise)
// ===========================================================================
__global__ void __launch_bounds__(256, 1) kB()
{
    const int h = blockIdx.x, idx = blockIdx.y * 256 + threadIdx.x;  // < 9216
    float* base = g_S + (size_t)h * NC * MF * VP + idx;
    float v[NC];
    #pragma unroll
    for (int c = 0; c < NC; c++) v[c] = base[c * (MF * VP)];
    float run = 0.f;
    #pragma unroll
    for (int c = 0; c < NC; c++) { base[c * (MF * VP)] = run; run += v[c]; }
}

// ===========================================================================
// Kernel C (256 thr, verbatim from the 41.5us R5 run): recompute phi_k, phi_q;
// scores = mask(phiQ·phiK^T); [out|norm] = phiQ·St+ + Sc·V+
// ===========================================================================
#define C_KQ  0                      // 128x68 = 8704 -> later St 128x72 @0
#define C_F   8704                   // 64x136 = 8704 -> later (St spills into)
#define C_ST  0                      // 128x72 = 9216
#define C_V   9216                   // 128x72 = 9216
#define C_PQ  18432                  // 128x132 = 16896
#define C_PK  35328                  // 128x136 = 17408 (later Sc 128x132)
#define C_SMW 52736
#define C_SMB (C_SMW * 4)

__global__ void __launch_bounds__(256, 1)
kC(const float* __restrict__ queries, const float* __restrict__ keys,
   const float* __restrict__ values, const float* __restrict__ feat,
   float* __restrict__ out)
{
    extern __shared__ uint32_t sm[];
    const int t = threadIdx.x, w = t >> 5, lane = t & 31;
    const int g = lane >> 2, tg = lane & 3;
    const int c = blockIdx.x, h = blockIdx.y, nbase = c * CHUNK;

    // a) stage K, F
    for (int idx = t; idx < DK * CHUNK; idx += 256) {
        int i = idx & 127, d = idx >> 7;
        sm[C_KQ + i * STR_KQ + d] = f2tf(keys[(h * DK + d) * NSEQ + nbase + i]);
    }
    for (int idx = t; idx < MF * DK; idx += 256) {
        int d = idx & 63, m = idx >> 6;
        sm[C_F + d * STR_F + m] = f2tf(feat[m * DK + d]);
    }
    __syncthreads();

    const int pm0 = (w & 3) * 32, pn0 = (w >> 2) * 64;

    // b) GEMM phi_k (frags)
    float DP[2][8][4] = {};
    for (int kk = 0; kk < 64; kk += 8) {
        uint32_t A[2][4], B[8][2];
        #pragma unroll
        for (int ms = 0; ms < 2; ms++) {
            int r0 = pm0 + ms * 16 + g;
            A[ms][0] = sm[C_KQ + r0 * STR_KQ + kk + tg];
            A[ms][1] = sm[C_KQ + (r0 + 8) * STR_KQ + kk + tg];
            A[ms][2] = sm[C_KQ + r0 * STR_KQ + kk + tg + 4];
            A[ms][3] = sm[C_KQ + (r0 + 8) * STR_KQ + kk + tg + 4];
        }
        #pragma unroll
        for (int ns = 0; ns < 8; ns++) {
            B[ns][0] = sm[C_F + (kk + tg) * STR_F + pn0 + ns * 8 + g];
            B[ns][1] = sm[C_F + (kk + tg + 4) * STR_F + pn0 + ns * 8 + g];
        }
        #pragma unroll
        for (int ms = 0; ms < 2; ms++)
            #pragma unroll
            for (int ns = 0; ns < 8; ns++) mma8(DP[ms][ns], A[ms], B[ns]);
    }
    __syncthreads();   // all reads of K done

    // c) epilogue phi_k -> sPK[m][j] (transposed); restage Q into C_KQ
    #pragma unroll
    for (int ms = 0; ms < 2; ms++)
        #pragma unroll
        for (int ns = 0; ns < 8; ns++)
            #pragma unroll
            for (int e = 0; e < 4; e++) {
                int rj = pm0 + ms * 16 + g + ((e >> 1) << 3);
                int cm = pn0 + ns * 8 + tg * 2 + (e & 1);
                sm[C_PK + cm * STR_PK + rj] =
                    f2tf(fmaxf(DP[ms][ns][e], 0.f) * PHI_SCALE);
            }
    for (int idx = t; idx < DK * CHUNK; idx += 256) {
        int i = idx & 127, d = idx >> 7;
        sm[C_KQ + i * STR_KQ + d] = f2tf(queries[(h * DK + d) * NSEQ + nbase + i]);
    }
    __syncthreads();

    // d) GEMM phi_q (frags)
    #pragma unroll
    for (int ms = 0; ms < 2; ms++)
        #pragma unroll
        for (int ns = 0; ns < 8; ns++)
            #pragma unroll
            for (int e = 0; e < 4; e++) DP[ms][ns][e] = 0.f;
    for (int kk = 0; kk < 64; kk += 8) {
        uint32_t A[2][4], B[8][2];
        #pragma unroll
        for (int ms = 0; ms < 2; ms++) {
            int r0 = pm0 + ms * 16 + g;
            A[ms][0] = sm[C_KQ + r0 * STR_KQ + kk + tg];
            A[ms][1] = sm[C_KQ + (r0 + 8) * STR_KQ + kk + tg];
            A[ms][2] = sm[C_KQ + r0 * STR_KQ + kk + tg + 4];
            A[ms][3] = sm[C_KQ + (r0 + 8) * STR_KQ + kk + tg + 4];
        }
        #pragma unroll
        for (int ns = 0; ns < 8; ns++) {
            B[ns][0] = sm[C_F + (kk + tg) * STR_F + pn0 + ns * 8 + g];
            B[ns][1] = sm[C_F + (kk + tg + 4) * STR_F + pn0 + ns * 8 + g];
        }
        #pragma unroll
        for (int ms = 0; ms < 2; ms++)
            #pragma unroll
            for (int ns = 0; ns < 8; ns++) mma8(DP[ms][ns], A[ms], B[ns]);
    }
    __syncthreads();   // all reads of Q/F done -> C_KQ/C_F reusable

    // e) epilogue phi_q -> sPQ[i][m]; stage St+ (prefix [S|z]) and V+
    #pragma unroll
    for (int ms = 0; ms < 2; ms++)
        #pragma unroll
        for (int ns = 0; ns < 8; ns++)
            #pragma unroll
            for (int e = 0; e < 4; e++) {
                int ri = pm0 + ms * 16 + g + ((e >> 1) << 3);
                int cm = pn0 + ns * 8 + tg * 2 + (e & 1);
                sm[C_PQ + ri * STR_PQ + cm] =
                    f2tf(fmaxf(DP[ms][ns][e], 0.f) * PHI_SCALE);
            }
    {
        const float* Sg = g_S + (size_t)(h * NC + c) * MF * VP;
        for (int idx = t; idx < MF * VP; idx += 256)
            sm[C_ST + idx] = f2tf(Sg[idx]);          // [m][v], stride 72 native
        for (int idx = t; idx < DVV * CHUNK; idx += 256) {
            int j = idx & 127, v = idx >> 7;
            sm[C_V + j * STR_V + v] = f2tf(values[(h * DVV + v) * NSEQ + nbase + j]);
        }
        for (int idx = t; idx < CHUNK * 8; idx += 256) {
            int j = idx >> 3, v = 64 + (idx & 7);
            sm[C_V + j * STR_V + v] = (v == 64) ? 0x3F800000u : 0u;
        }
    }
    __syncthreads();

    // f) GEMM scores: A=sPQ, B=sPK, K=128 (frags in DP)
    #pragma unroll
    for (int ms = 0; ms < 2; ms++)
        #pragma unroll
        for (int ns = 0; ns < 8; ns++)
            #pragma unroll
            for (int e = 0; e < 4; e++) DP[ms][ns][e] = 0.f;
    for (int kk = 0; kk < CHUNK; kk += 8) {
        uint32_t A[2][4], B[8][2];
        #pragma unroll
        for (int ms = 0; ms < 2; ms++) {
            int r0 = pm0 + ms * 16 + g;
            A[ms][0] = sm[C_PQ + r0 * STR_PQ + kk + tg];
            A[ms][1] = sm[C_PQ + (r0 + 8) * STR_PQ + kk + tg];
            A[ms][2] = sm[C_PQ + r0 * STR_PQ + kk + tg + 4];
            A[ms][3] = sm[C_PQ + (r0 + 8) * STR_PQ + kk + tg + 4];
        }
        #pragma unroll
        for (int ns = 0; ns < 8; ns++) {
            B[ns][0] = sm[C_PK + (kk + tg) * STR_PK + pn0 + ns * 8 + g];
            B[ns][1] = sm[C_PK + (kk + tg + 4) * STR_PK + pn0 + ns * 8 + g];
        }
        #pragma unroll
        for (int ms = 0; ms < 2; ms++)
            #pragma unroll
            for (int ns = 0; ns < 8; ns++) mma8(DP[ms][ns], A[ms], B[ns]);
    }
    __syncthreads();   // all reads of sPK done

    // g) epilogue scores: causal mask -> sSc[i][j] (overwrites C_PK region)
    #pragma unroll
    for (int ms = 0; ms < 2; ms++)
        #pragma unroll
        for (int ns = 0; ns < 8; ns++)
            #pragma unroll
            for (int e = 0; e < 4; e++) {
                int ri = pm0 + ms * 16 + g + ((e >> 1) << 3);
                int cj = pn0 + ns * 8 + tg * 2 + (e & 1);
                float s = (cj <= ri) ? DP[ms][ns][e] : 0.f;
                sm[C_PK + ri * STR_SC + cj] = f2tf(s);
            }
    __syncthreads();

    // h) GEMM out: [out|norm][i][v+] = phiQ.St+ + Sc.V+ ; warp tile 16x72
    {
        const int i0 = w * 16;
        float D[9][4] = {};
        for (int kk = 0; kk < CHUNK; kk += 8) {       // pass 1: phiQ . St+
            uint32_t A[4];
            A[0] = sm[C_PQ + (i0 + g) * STR_PQ + kk + tg];
            A[1] = sm[C_PQ + (i0 + g + 8) * STR_PQ + kk + tg];
            A[2] = sm[C_PQ + (i0 + g) * STR_PQ + kk + tg + 4];
            A[3] = sm[C_PQ + (i0 + g + 8) * STR_PQ + kk + tg + 4];
            #pragma unroll
            for (int ns = 0; ns < 9; ns++) {
                uint32_t B[2];
                B[0] = sm[C_ST + (kk + tg) * STR_ST + ns * 8 + g];
                B[1] = sm[C_ST + (kk + tg + 4) * STR_ST + ns * 8 + g];
                mma8(D[ns], A, B);
            }
        }
        for (int kk = 0; kk < CHUNK; kk += 8) {       // pass 2: Sc . V+
            uint32_t A[4];
            A[0] = sm[C_PK + (i0 + g) * STR_SC + kk + tg];
            A[1] = sm[C_PK + (i0 + g + 8) * STR_SC + kk + tg];
            A[2] = sm[C_PK + (i0 + g) * STR_SC + kk + tg + 4];
            A[3] = sm[C_PK + (i0 + g + 8) * STR_SC + kk + tg + 4];
            #pragma unroll
            for (int ns = 0; ns < 9; ns++) {
                uint32_t B[2];
                B[0] = sm[C_V + (kk + tg) * STR_V + ns * 8 + g];
                B[1] = sm[C_V + (kk + tg + 4) * STR_V + ns * 8 + g];
                mma8(D[ns], A, B);
            }
        }
        // i) norm = column 64 (ns=8, tg=0, e=0/2) -> broadcast within row group
        float nlo = __shfl_sync(0xffffffffu, D[8][0], lane & 28);
        float nhi = __shfl_sync(0xffffffffu, D[8][2], lane & 28);
        float ilo = 1.f / nlo, ihi = 1.f / nhi;
        #pragma unroll
        for (int ns = 0; ns < 8; ns++)
            #pragma unroll
            for (int e = 0; e < 4; e++) {
                int ri = i0 + g + ((e >> 1) << 3);
                int v  = ns * 8 + tg * 2 + (e & 1);
                out[(h * DVV + v) * NSEQ + nbase + ri] =
                    D[ns][e] * ((e >> 1) ? ihi : ilo);
            }
    }
}

// ===========================================================================
extern "C" void kernel_launch(void* const* d_in, const int* in_sizes, int n_in,
                              void* d_out, int out_size)
{
    const float* keys    = (const float*)d_in[0];
    const float* values  = (const float*)d_in[1];
    const float* queries = (const float*)d_in[2];
    const float* feat    = (const float*)d_in[3];
    float* out = (float*)d_out;

    cudaFuncSetAttribute(kA, cudaFuncAttributeMaxDynamicSharedMemorySize, A_SMB);
    cudaFuncSetAttribute(kC, cudaFuncAttributeMaxDynamicSharedMemorySize, C_SMB);

    kA<<<dim3(NC, BH), 512, A_SMB>>>(keys, values, feat);
    kB<<<dim3(BH, 36), 256>>>();
    kC<<<dim3(NC, BH), 256, C_SMB>>>(queries, keys, values, feat, out);
}

// round 10
// speedup vs baseline: 1.1189x; 1.1189x over previous
#include <cuda_runtime.h>
#include <cstdint>

#define BH    8
#define DK    64
#define DVV   64
#define NSEQ  2048
#define MF    128
#define CHUNK 128
#define NC    16
#define VP    72          // DV padded: col 64 = ones (z / norm), 65..71 = 0

#define PHI_SCALE 0.08838834764831845f   // 1/sqrt(128)

// Per-(head,chunk) fused state [S | z | pad] : [m][VP], fp32.
// kB converts to exclusive prefix over chunks.
__device__ float g_S[BH * NC * MF * VP];   // 4.7 MB

// ---------------------------------------------------------------------------
__device__ __forceinline__ uint32_t f2tf(float f) {
    uint32_t r; asm("cvt.rna.tf32.f32 %0, %1;" : "=r"(r) : "f"(f)); return r;
}
__device__ __forceinline__ void mma8(float* d, const uint32_t* A, const uint32_t* B) {
    asm volatile("mma.sync.aligned.m16n8k8.row.col.f32.tf32.tf32.f32 "
                 "{%0,%1,%2,%3}, {%4,%5,%6,%7}, {%8,%9}, {%0,%1,%2,%3};"
                 : "+f"(d[0]), "+f"(d[1]), "+f"(d[2]), "+f"(d[3])
                 : "r"(A[0]), "r"(A[1]), "r"(A[2]), "r"(A[3]), "r"(B[0]), "r"(B[1]));
}

// Fragment loaders. pA = &sm[base + (row0+g)*str + kk + tg] ;
// pB = &sm[base + (kk+tg)*str + n0 + g]
__device__ __forceinline__ void ldA2(uint32_t A[2][4], const uint32_t* p, int str) {
    A[0][0] = p[0];        A[0][1] = p[8 * str];
    A[0][2] = p[4];        A[0][3] = p[8 * str + 4];
    A[1][0] = p[16 * str]; A[1][1] = p[24 * str];
    A[1][2] = p[16 * str + 4]; A[1][3] = p[24 * str + 4];
}
__device__ __forceinline__ void ldA1(uint32_t A[4], const uint32_t* p, int str) {
    A[0] = p[0]; A[1] = p[8 * str]; A[2] = p[4]; A[3] = p[8 * str + 4];
}
__device__ __forceinline__ void ldB8(uint32_t B[8][2], const uint32_t* p, int str) {
    #pragma unroll
    for (int ns = 0; ns < 8; ns++) { B[ns][0] = p[ns * 8]; B[ns][1] = p[4 * str + ns * 8]; }
}
__device__ __forceinline__ void ldB9(uint32_t B[9][2], const uint32_t* p, int str) {
    #pragma unroll
    for (int ns = 0; ns < 9; ns++) { B[ns][0] = p[ns * 8]; B[ns][1] = p[4 * str + ns * 8]; }
}

// Smem strides (words): A-operand tiles ≡4 (mod 32); B-operand tiles ≡8 (mod 32).
#define STR_KQ 68    // [i][d]  A
#define STR_F  136   // [d][m]  B
#define STR_PT 132   // [m][i]  A (kA phi^T)
#define STR_V  72    // [i][v]  B
#define STR_PQ 132   // [i][m]  A
#define STR_PK 136   // [m][j]  B
#define STR_SC 132   // [i][j]  A
#define STR_ST 72    // [m][v]  B

// ===========================================================================
// Kernel A (256 thr): phi = relu(Kc F^T)*s ;  [S|z] = phi^T [V;1]
// ===========================================================================
#define A_K   0                       // 128 x 68  = 8704
#define A_F   8704                    // 64 x 136  = 8704
#define A_PT  17408                   // 128 x 132 = 16896
#define A_V   34304                   // 128 x 72  = 9216
#define A_SMW 43520
#define A_SMB (A_SMW * 4)

__global__ void __launch_bounds__(256, 1)
kA(const float* __restrict__ keys, const float* __restrict__ values,
   const float* __restrict__ feat)
{
    extern __shared__ uint32_t sm[];
    const int t = threadIdx.x, w = t >> 5, lane = t & 31;
    const int g = lane >> 2, tg = lane & 3;
    const int c = blockIdx.x, h = blockIdx.y, nbase = c * CHUNK;

    // Stage (tf32-rounded)
    for (int idx = t; idx < DK * CHUNK; idx += 256) {
        int i = idx & 127, d = idx >> 7;
        sm[A_K + i * STR_KQ + d] = f2tf(keys[(h * DK + d) * NSEQ + nbase + i]);
    }
    for (int idx = t; idx < MF * DK; idx += 256) {
        int d = idx & 63, m = idx >> 6;
        sm[A_F + d * STR_F + m] = f2tf(feat[m * DK + d]);
    }
    for (int idx = t; idx < DVV * CHUNK; idx += 256) {
        int i = idx & 127, v = idx >> 7;
        sm[A_V + i * STR_V + v] = f2tf(values[(h * DVV + v) * NSEQ + nbase + i]);
    }
    for (int idx = t; idx < CHUNK * 8; idx += 256) {
        int i = idx >> 3, v = 64 + (idx & 7);
        sm[A_V + i * STR_V + v] = (v == 64) ? 0x3F800000u : 0u;
    }
    __syncthreads();

    // GEMM1: phi[i][m], K=64; warp tile 32x64; double-buffered fragments
    {
        const int m0 = (w & 3) * 32, n0 = (w >> 2) * 64;
        float D[2][8][4] = {};
        uint32_t Ab[2][2][4], Bb[2][8][2];
        const uint32_t* pa = sm + A_K + (m0 + g) * STR_KQ + tg;
        const uint32_t* pb = sm + A_F + tg * STR_F + n0 + g;
        ldA2(Ab[0], pa, STR_KQ);
        ldB8(Bb[0], pb, STR_F);
        #pragma unroll
        for (int ks = 0; ks < 8; ks++) {
            const int cur = ks & 1;
            if (ks < 7) {
                ldA2(Ab[cur ^ 1], pa + (ks + 1) * 8, STR_KQ);
                ldB8(Bb[cur ^ 1], pb + (ks + 1) * 8 * STR_F, STR_F);
            }
            #pragma unroll
            for (int ms = 0; ms < 2; ms++)
                #pragma unroll
                for (int ns = 0; ns < 8; ns++) mma8(D[ms][ns], Ab[cur][ms], Bb[cur][ns]);
        }
        // Epilogue: relu*scale -> phiT[m][i]
        #pragma unroll
        for (int ms = 0; ms < 2; ms++)
            #pragma unroll
            for (int ns = 0; ns < 8; ns++)
                #pragma unroll
                for (int e = 0; e < 4; e++) {
                    int row = m0 + ms * 16 + g + ((e >> 1) << 3);
                    int col = n0 + ns * 8 + tg * 2 + (e & 1);
                    sm[A_PT + col * STR_PT + row] =
                        f2tf(fmaxf(D[ms][ns][e], 0.f) * PHI_SCALE);
                }
    }
    __syncthreads();

    // GEMM2: [S|z][m][v+], K=128; warp tile 16x72; double-buffered
    {
        const int m0 = w * 16;
        float D[9][4] = {};
        uint32_t Ab[2][4], Bb[2][9][2];
        const uint32_t* pa = sm + A_PT + (m0 + g) * STR_PT + tg;
        const uint32_t* pb = sm + A_V + tg * STR_V + g;
        ldA1(Ab[0], pa, STR_PT);
        ldB9(Bb[0], pb, STR_V);
        #pragma unroll
        for (int ks = 0; ks < 16; ks++) {
            const int cur = ks & 1;
            if (ks < 15) {
                ldA1(Ab[cur ^ 1], pa + (ks + 1) * 8, STR_PT);
                ldB9(Bb[cur ^ 1], pb + (ks + 1) * 8 * STR_V, STR_V);
            }
            #pragma unroll
            for (int ns = 0; ns < 9; ns++) mma8(D[ns], Ab[cur], Bb[cur][ns]);
        }
        float* Sg = g_S + (size_t)(h * NC + c) * MF * VP;
        #pragma unroll
        for (int ns = 0; ns < 9; ns++)
            #pragma unroll
            for (int e = 0; e < 4; e++) {
                int row = m0 + g + ((e >> 1) << 3);
                int col = ns * 8 + tg * 2 + (e & 1);
                Sg[row * VP + col] = D[ns][e];
            }
    }
}

// ===========================================================================
// Kernel B: exclusive prefix over chunks of g_S (elementwise)
// ===========================================================================
__global__ void __launch_bounds__(256, 1) kB()
{
    const int h = blockIdx.x, idx = blockIdx.y * 256 + threadIdx.x;  // < 9216
    float* base = g_S + (size_t)h * NC * MF * VP + idx;
    float v[NC];
    #pragma unroll
    for (int c = 0; c < NC; c++) v[c] = base[c * (MF * VP)];
    float run = 0.f;
    #pragma unroll
    for (int c = 0; c < NC; c++) { base[c * (MF * VP)] = run; run += v[c]; }
}

// ===========================================================================
// Kernel C (256 thr): phi_k, phi_q, scores (masked, skip-aware),
// [out|norm] = phiQ·St+ + Sc·V+ (pass-2 truncated at the diagonal)
// ===========================================================================
#define C_KQ  0                      // 128x68 = 8704 -> later St 128x72 @0
#define C_F   8704                   // 64x136 = 8704
#define C_ST  0                      // 128x72 = 9216
#define C_V   9216                   // 128x72 = 9216
#define C_PQ  18432                  // 128x132 = 16896
#define C_PK  35328                  // 128x136 = 17408 (later Sc 128x132)
#define C_SMW 52736
#define C_SMB (C_SMW * 4)

__global__ void __launch_bounds__(256, 1)
kC(const float* __restrict__ queries, const float* __restrict__ keys,
   const float* __restrict__ values, const float* __restrict__ feat,
   float* __restrict__ out)
{
    extern __shared__ uint32_t sm[];
    const int t = threadIdx.x, w = t >> 5, lane = t & 31;
    const int g = lane >> 2, tg = lane & 3;
    const int c = blockIdx.x, h = blockIdx.y, nbase = c * CHUNK;

    // a) stage K, F
    for (int idx = t; idx < DK * CHUNK; idx += 256) {
        int i = idx & 127, d = idx >> 7;
        sm[C_KQ + i * STR_KQ + d] = f2tf(keys[(h * DK + d) * NSEQ + nbase + i]);
    }
    for (int idx = t; idx < MF * DK; idx += 256) {
        int d = idx & 63, m = idx >> 6;
        sm[C_F + d * STR_F + m] = f2tf(feat[m * DK + d]);
    }
    __syncthreads();

    const int pm0 = (w & 3) * 32, pn0 = (w >> 2) * 64;

    // b) GEMM phi_k (32x64, K=64, double-buffered)
    float DP[2][8][4] = {};
    {
        uint32_t Ab[2][2][4], Bb[2][8][2];
        const uint32_t* pa = sm + C_KQ + (pm0 + g) * STR_KQ + tg;
        const uint32_t* pb = sm + C_F + tg * STR_F + pn0 + g;
        ldA2(Ab[0], pa, STR_KQ);
        ldB8(Bb[0], pb, STR_F);
        #pragma unroll
        for (int ks = 0; ks < 8; ks++) {
            const int cur = ks & 1;
            if (ks < 7) {
                ldA2(Ab[cur ^ 1], pa + (ks + 1) * 8, STR_KQ);
                ldB8(Bb[cur ^ 1], pb + (ks + 1) * 8 * STR_F, STR_F);
            }
            #pragma unroll
            for (int ms = 0; ms < 2; ms++)
                #pragma unroll
                for (int ns = 0; ns < 8; ns++) mma8(DP[ms][ns], Ab[cur][ms], Bb[cur][ns]);
        }
    }
    __syncthreads();   // all reads of K done

    // c) epilogue phi_k -> sPK[m][j] (transposed); restage Q into C_KQ
    #pragma unroll
    for (int ms = 0; ms < 2; ms++)
        #pragma unroll
        for (int ns = 0; ns < 8; ns++)
            #pragma unroll
            for (int e = 0; e < 4; e++) {
                int rj = pm0 + ms * 16 + g + ((e >> 1) << 3);
                int cm = pn0 + ns * 8 + tg * 2 + (e & 1);
                sm[C_PK + cm * STR_PK + rj] =
                    f2tf(fmaxf(DP[ms][ns][e], 0.f) * PHI_SCALE);
            }
    for (int idx = t; idx < DK * CHUNK; idx += 256) {
        int i = idx & 127, d = idx >> 7;
        sm[C_KQ + i * STR_KQ + d] = f2tf(queries[(h * DK + d) * NSEQ + nbase + i]);
    }
    __syncthreads();

    // d) GEMM phi_q (32x64, K=64, double-buffered)
    #pragma unroll
    for (int ms = 0; ms < 2; ms++)
        #pragma unroll
        for (int ns = 0; ns < 8; ns++)
            #pragma unroll
            for (int e = 0; e < 4; e++) DP[ms][ns][e] = 0.f;
    {
        uint32_t Ab[2][2][4], Bb[2][8][2];
        const uint32_t* pa = sm + C_KQ + (pm0 + g) * STR_KQ + tg;
        const uint32_t* pb = sm + C_F + tg * STR_F + pn0 + g;
        ldA2(Ab[0], pa, STR_KQ);
        ldB8(Bb[0], pb, STR_F);
        #pragma unroll
        for (int ks = 0; ks < 8; ks++) {
            const int cur = ks & 1;
            if (ks < 7) {
                ldA2(Ab[cur ^ 1], pa + (ks + 1) * 8, STR_KQ);
                ldB8(Bb[cur ^ 1], pb + (ks + 1) * 8 * STR_F, STR_F);
            }
            #pragma unroll
            for (int ms = 0; ms < 2; ms++)
                #pragma unroll
                for (int ns = 0; ns < 8; ns++) mma8(DP[ms][ns], Ab[cur][ms], Bb[cur][ns]);
        }
    }
    __syncthreads();   // all reads of Q/F done -> C_KQ/C_F reusable

    // e) epilogue phi_q -> sPQ[i][m]; stage St+ (prefix [S|z]) and V+
    #pragma unroll
    for (int ms = 0; ms < 2; ms++)
        #pragma unroll
        for (int ns = 0; ns < 8; ns++)
            #pragma unroll
            for (int e = 0; e < 4; e++) {
                int ri = pm0 + ms * 16 + g + ((e >> 1) << 3);
                int cm = pn0 + ns * 8 + tg * 2 + (e & 1);
                sm[C_PQ + ri * STR_PQ + cm] =
                    f2tf(fmaxf(DP[ms][ns][e], 0.f) * PHI_SCALE);
            }
    {
        const float* Sg = g_S + (size_t)(h * NC + c) * MF * VP;
        for (int idx = t; idx < MF * VP; idx += 256)
            sm[C_ST + idx] = f2tf(Sg[idx]);          // [m][v], stride 72 native
        for (int idx = t; idx < DVV * CHUNK; idx += 256) {
            int j = idx & 127, v = idx >> 7;
            sm[C_V + j * STR_V + v] = f2tf(values[(h * DVV + v) * NSEQ + nbase + j]);
        }
        for (int idx = t; idx < CHUNK * 8; idx += 256) {
            int j = idx >> 3, v = 64 + (idx & 7);
            sm[C_V + j * STR_V + v] = (v == 64) ? 0x3F800000u : 0u;
        }
    }
    __syncthreads();

    // f) GEMM scores: A=sPQ, B=sPK, K=128, double-buffered.
    // Warps whose whole tile is above the diagonal (w = 4, 5) skip: DP stays 0.
    #pragma unroll
    for (int ms = 0; ms < 2; ms++)
        #pragma unroll
        for (int ns = 0; ns < 8; ns++)
            #pragma unroll
            for (int e = 0; e < 4; e++) DP[ms][ns][e] = 0.f;
    if (pn0 <= pm0 + 31) {
        uint32_t Ab[2][2][4], Bb[2][8][2];
        const uint32_t* pa = sm + C_PQ + (pm0 + g) * STR_PQ + tg;
        const uint32_t* pb = sm + C_PK + tg * STR_PK + pn0 + g;
        ldA2(Ab[0], pa, STR_PQ);
        ldB8(Bb[0], pb, STR_PK);
        #pragma unroll
        for (int ks = 0; ks < 16; ks++) {
            const int cur = ks & 1;
            if (ks < 15) {
                ldA2(Ab[cur ^ 1], pa + (ks + 1) * 8, STR_PQ);
                ldB8(Bb[cur ^ 1], pb + (ks + 1) * 8 * STR_PK, STR_PK);
            }
            #pragma unroll
            for (int ms = 0; ms < 2; ms++)
                #pragma unroll
                for (int ns = 0; ns < 8; ns++) mma8(DP[ms][ns], Ab[cur][ms], Bb[cur][ns]);
        }
    }
    __syncthreads();   // all reads of sPK done

    // g) epilogue scores: causal mask -> sSc[i][j] (overwrites C_PK region)
    #pragma unroll
    for (int ms = 0; ms < 2; ms++)
        #pragma unroll
        for (int ns = 0; ns < 8; ns++)
            #pragma unroll
            for (int e = 0; e < 4; e++) {
                int ri = pm0 + ms * 16 + g + ((e >> 1) << 3);
                int cj = pn0 + ns * 8 + tg * 2 + (e & 1);
                float s = (cj <= ri) ? DP[ms][ns][e] : 0.f;
                sm[C_PK + ri * STR_SC + cj] = f2tf(s);
            }
    __syncthreads();

    // h) GEMM out: [out|norm][i][v+] = phiQ.St+ + Sc.V+ ; warp tile 16x72
    {
        const int i0 = w * 16;
        float D[9][4] = {};
        {   // pass 1: phiQ . St+, K=128, double-buffered
            uint32_t Ab[2][4], Bb[2][9][2];
            const uint32_t* pa = sm + C_PQ + (i0 + g) * STR_PQ + tg;
            const uint32_t* pb = sm + C_ST + tg * STR_ST + g;
            ldA1(Ab[0], pa, STR_PQ);
            ldB9(Bb[0], pb, STR_ST);
            #pragma unroll
            for (int ks = 0; ks < 16; ks++) {
                const int cur = ks & 1;
                if (ks < 15) {
                    ldA1(Ab[cur ^ 1], pa + (ks + 1) * 8, STR_PQ);
                    ldB9(Bb[cur ^ 1], pb + (ks + 1) * 8 * STR_ST, STR_ST);
                }
                #pragma unroll
                for (int ns = 0; ns < 9; ns++) mma8(D[ns], Ab[cur], Bb[cur][ns]);
            }
        }
        {   // pass 2: Sc . V+, K truncated at the diagonal (Sc[i][j]=0 for j>i)
            const int ksteps = (i0 + 16) >> 3;    // 2..16
            uint32_t Ab[2][4], Bb[2][9][2];
            const uint32_t* pa = sm + C_PK + (i0 + g) * STR_SC + tg;
            const uint32_t* pb = sm + C_V + tg * STR_V + g;
            ldA1(Ab[0], pa, STR_SC);
            ldB9(Bb[0], pb, STR_V);
            for (int ks = 0; ks < ksteps; ks++) {
                const int cur = ks & 1;
                if (ks + 1 < ksteps) {
                    ldA1(Ab[cur ^ 1], pa + (ks + 1) * 8, STR_SC);
                    ldB9(Bb[cur ^ 1], pb + (ks + 1) * 8 * STR_V, STR_V);
                }
                #pragma unroll
                for (int ns = 0; ns < 9; ns++) mma8(D[ns], Ab[cur], Bb[cur][ns]);
            }
        }
        // i) norm = column 64 (ns=8, tg=0, e=0/2) -> broadcast within row group
        float nlo = __shfl_sync(0xffffffffu, D[8][0], lane & 28);
        float nhi = __shfl_sync(0xffffffffu, D[8][2], lane & 28);
        float ilo = 1.f / nlo, ihi = 1.f / nhi;
        #pragma unroll
        for (int ns = 0; ns < 8; ns++)
            #pragma unroll
            for (int e = 0; e < 4; e++) {
                int ri = i0 + g + ((e >> 1) << 3);
                int v  = ns * 8 + tg * 2 + (e & 1);
                out[(h * DVV + v) * NSEQ + nbase + ri] =
                    D[ns][e] * ((e >> 1) ? ihi : ilo);
            }
    }
}

// ===========================================================================
extern "C" void kernel_launch(void* const* d_in, const int* in_sizes, int n_in,
                              void* d_out, int out_size)
{
    const float* keys    = (const float*)d_in[0];
    const float* values  = (const float*)d_in[1];
    const float* queries = (const float*)d_in[2];
    const float* feat    = (const float*)d_in[3];
    float* out = (float*)d_out;

    cudaFuncSetAttribute(kA, cudaFuncAttributeMaxDynamicSharedMemorySize, A_SMB);
    cudaFuncSetAttribute(kC, cudaFuncAttributeMaxDynamicSharedMemorySize, C_SMB);

    kA<<<dim3(NC, BH), 256, A_SMB>>>(keys, values, feat);
    kB<<<dim3(BH, 36), 256>>>();
    kC<<<dim3(NC, BH), 256, C_SMB>>>(queries, keys, values, feat, out);
}

// round 11
// speedup vs baseline: 1.5980x; 1.4282x over previous
#include <cuda_runtime.h>
#include <cstdint>

#define BH    8
#define DK    64
#define DVV   64
#define NSEQ  2048
#define MF    128
#define CHUNK 128
#define NC    16
#define VP    72          // DV padded: col 64 = ones (z / norm), 65..71 = 0

#define PHI_SCALE 0.08838834764831845f   // 1/sqrt(128)

// Per-(head,chunk) fused state [S | z | pad] : [m][VP], fp32.
// kB converts to exclusive prefix over chunks.
__device__ float g_S[BH * NC * MF * VP];   // 4.7 MB

// ---------------------------------------------------------------------------
__device__ __forceinline__ uint32_t f2tf(float f) {
    uint32_t r; asm("cvt.rna.tf32.f32 %0, %1;" : "=r"(r) : "f"(f)); return r;
}
__device__ __forceinline__ void mma8(float* d, const uint32_t* A, const uint32_t* B) {
    asm volatile("mma.sync.aligned.m16n8k8.row.col.f32.tf32.tf32.f32 "
                 "{%0,%1,%2,%3}, {%4,%5,%6,%7}, {%8,%9}, {%0,%1,%2,%3};"
                 : "+f"(d[0]), "+f"(d[1]), "+f"(d[2]), "+f"(d[3])
                 : "r"(A[0]), "r"(A[1]), "r"(A[2]), "r"(A[3]), "r"(B[0]), "r"(B[1]));
}

// Smem strides (words), chosen so fragment LDS are bank-conflict-free:
// A-operand row stride ≡ 4 (mod 32); B-operand row stride ≡ 8 (mod 32).
#define STR_KQ 68    // [i][d]  A
#define STR_F  136   // [d][m]  B
#define STR_PT 132   // [m][i]  A (kA phi^T)
#define STR_V  72    // [i][v]  B
#define STR_PQ 132   // [i][m]  A
#define STR_PK 136   // [m][j]  B
#define STR_SC 132   // [i][j]  A
#define STR_ST 72    // [m][v]  B

// ===========================================================================
// Kernel A: per (h,c): phi = relu(Kc F^T)*s ;  [S|z] = phi^T [V;1]
// ===========================================================================
#define A_K   0                       // 128 x 68  = 8704
#define A_F   8704                    // 64 x 136  = 8704
#define A_PT  17408                   // 128 x 132 = 16896
#define A_V   34304                   // 128 x 72  = 9216
#define A_SMW 43520
#define A_SMB (A_SMW * 4)

__global__ void __launch_bounds__(256, 1)
kA(const float* __restrict__ keys, const float* __restrict__ values,
   const float* __restrict__ feat)
{
    extern __shared__ uint32_t sm[];
    const int t = threadIdx.x, w = t >> 5, lane = t & 31;
    const int g = lane >> 2, tg = lane & 3;
    const int c = blockIdx.x, h = blockIdx.y, nbase = c * CHUNK;

    // Stage (tf32-rounded)
    for (int idx = t; idx < DK * CHUNK; idx += 256) {
        int i = idx & 127, d = idx >> 7;
        sm[A_K + i * STR_KQ + d] = f2tf(keys[(h * DK + d) * NSEQ + nbase + i]);
    }
    for (int idx = t; idx < MF * DK; idx += 256) {
        int d = idx & 63, m = idx >> 6;
        sm[A_F + d * STR_F + m] = f2tf(feat[m * DK + d]);
    }
    for (int idx = t; idx < DVV * CHUNK; idx += 256) {
        int i = idx & 127, v = idx >> 7;
        sm[A_V + i * STR_V + v] = f2tf(values[(h * DVV + v) * NSEQ + nbase + i]);
    }
    for (int idx = t; idx < CHUNK * 8; idx += 256) {
        int i = idx >> 3, v = 64 + (idx & 7);
        sm[A_V + i * STR_V + v] = (v == 64) ? 0x3F800000u : 0u;
    }
    __syncthreads();

    // GEMM1: phi[i][m], K=64; warp tile 32x64
    {
        const int m0 = (w & 3) * 32, n0 = (w >> 2) * 64;
        float D[2][8][4] = {};
        for (int kk = 0; kk < 64; kk += 8) {
            uint32_t A[2][4], B[8][2];
            #pragma unroll
            for (int ms = 0; ms < 2; ms++) {
                int r0 = m0 + ms * 16 + g;
                A[ms][0] = sm[A_K + r0 * STR_KQ + kk + tg];
                A[ms][1] = sm[A_K + (r0 + 8) * STR_KQ + kk + tg];
                A[ms][2] = sm[A_K + r0 * STR_KQ + kk + tg + 4];
                A[ms][3] = sm[A_K + (r0 + 8) * STR_KQ + kk + tg + 4];
            }
            #pragma unroll
            for (int ns = 0; ns < 8; ns++) {
                B[ns][0] = sm[A_F + (kk + tg) * STR_F + n0 + ns * 8 + g];
                B[ns][1] = sm[A_F + (kk + tg + 4) * STR_F + n0 + ns * 8 + g];
            }
            #pragma unroll
            for (int ms = 0; ms < 2; ms++)
                #pragma unroll
                for (int ns = 0; ns < 8; ns++) mma8(D[ms][ns], A[ms], B[ns]);
        }
        // Epilogue: relu*scale -> phiT[m][i]
        #pragma unroll
        for (int ms = 0; ms < 2; ms++)
            #pragma unroll
            for (int ns = 0; ns < 8; ns++)
                #pragma unroll
                for (int e = 0; e < 4; e++) {
                    int row = m0 + ms * 16 + g + ((e >> 1) << 3);
                    int col = n0 + ns * 8 + tg * 2 + (e & 1);
                    sm[A_PT + col * STR_PT + row] =
                        f2tf(fmaxf(D[ms][ns][e], 0.f) * PHI_SCALE);
                }
    }
    __syncthreads();

    // GEMM2: [S|z][m][v+], K=128; warp tile 16x72
    {
        const int m0 = w * 16;
        float D[9][4] = {};
        for (int kk = 0; kk < CHUNK; kk += 8) {
            uint32_t A[4];
            A[0] = sm[A_PT + (m0 + g) * STR_PT + kk + tg];
            A[1] = sm[A_PT + (m0 + g + 8) * STR_PT + kk + tg];
            A[2] = sm[A_PT + (m0 + g) * STR_PT + kk + tg + 4];
            A[3] = sm[A_PT + (m0 + g + 8) * STR_PT + kk + tg + 4];
            #pragma unroll
            for (int ns = 0; ns < 9; ns++) {
                uint32_t B[2];
                B[0] = sm[A_V + (kk + tg) * STR_V + ns * 8 + g];
                B[1] = sm[A_V + (kk + tg + 4) * STR_V + ns * 8 + g];
                mma8(D[ns], A, B);
            }
        }
        float* Sg = g_S + (size_t)(h * NC + c) * MF * VP;
        #pragma unroll
        for (int ns = 0; ns < 9; ns++)
            #pragma unroll
            for (int e = 0; e < 4; e++) {
                int row = m0 + g + ((e >> 1) << 3);
                int col = ns * 8 + tg * 2 + (e & 1);
                Sg[row * VP + col] = D[ns][e];
            }
    }
}

// ===========================================================================
// Kernel B: exclusive prefix over chunks of g_S (elementwise)
// ===========================================================================
__global__ void __launch_bounds__(256, 1) kB()
{
    const int h = blockIdx.x, idx = blockIdx.y * 256 + threadIdx.x;  // < 9216
    float* base = g_S + (size_t)h * NC * MF * VP + idx;
    float v[NC];
    #pragma unroll
    for (int c = 0; c < NC; c++) v[c] = base[c * (MF * VP)];
    float run = 0.f;
    #pragma unroll
    for (int c = 0; c < NC; c++) { base[c * (MF * VP)] = run; run += v[c]; }
}

// ===========================================================================
// Kernel C: phi_k, phi_q, scores (masked, causal-skip), out = phiQ.S+ + Sc.V+
// (pass 2 truncated at the diagonal), norm, store
// ===========================================================================
#define C_KQ  0                      // 128x68 = 8704 -> later St 128x72 @0
#define C_F   8704                   // 64x136 = 8704 -> later (St spills into)
#define C_ST  0                      // 128x72 = 9216
#define C_V   9216                   // 128x72 = 9216
#define C_PQ  18432                  // 128x132 = 16896
#define C_PK  35328                  // 128x136 = 17408 (later Sc 128x132)
#define C_SMW 52736
#define C_SMB (C_SMW * 4)

__global__ void __launch_bounds__(256, 1)
kC(const float* __restrict__ queries, const float* __restrict__ keys,
   const float* __restrict__ values, const float* __restrict__ feat,
   float* __restrict__ out)
{
    extern __shared__ uint32_t sm[];
    const int t = threadIdx.x, w = t >> 5, lane = t & 31;
    const int g = lane >> 2, tg = lane & 3;
    const int c = blockIdx.x, h = blockIdx.y, nbase = c * CHUNK;

    // a) stage K, F
    for (int idx = t; idx < DK * CHUNK; idx += 256) {
        int i = idx & 127, d = idx >> 7;
        sm[C_KQ + i * STR_KQ + d] = f2tf(keys[(h * DK + d) * NSEQ + nbase + i]);
    }
    for (int idx = t; idx < MF * DK; idx += 256) {
        int d = idx & 63, m = idx >> 6;
        sm[C_F + d * STR_F + m] = f2tf(feat[m * DK + d]);
    }
    __syncthreads();

    const int pm0 = (w & 3) * 32, pn0 = (w >> 2) * 64;

    // b) GEMM phi_k (frags)
    float DP[2][8][4] = {};
    for (int kk = 0; kk < 64; kk += 8) {
        uint32_t A[2][4], B[8][2];
        #pragma unroll
        for (int ms = 0; ms < 2; ms++) {
            int r0 = pm0 + ms * 16 + g;
            A[ms][0] = sm[C_KQ + r0 * STR_KQ + kk + tg];
            A[ms][1] = sm[C_KQ + (r0 + 8) * STR_KQ + kk + tg];
            A[ms][2] = sm[C_KQ + r0 * STR_KQ + kk + tg + 4];
            A[ms][3] = sm[C_KQ + (r0 + 8) * STR_KQ + kk + tg + 4];
        }
        #pragma unroll
        for (int ns = 0; ns < 8; ns++) {
            B[ns][0] = sm[C_F + (kk + tg) * STR_F + pn0 + ns * 8 + g];
            B[ns][1] = sm[C_F + (kk + tg + 4) * STR_F + pn0 + ns * 8 + g];
        }
        #pragma unroll
        for (int ms = 0; ms < 2; ms++)
            #pragma unroll
            for (int ns = 0; ns < 8; ns++) mma8(DP[ms][ns], A[ms], B[ns]);
    }
    __syncthreads();   // all reads of K done

    // c) epilogue phi_k -> sPK[m][j] (transposed); restage Q into C_KQ
    #pragma unroll
    for (int ms = 0; ms < 2; ms++)
        #pragma unroll
        for (int ns = 0; ns < 8; ns++)
            #pragma unroll
            for (int e = 0; e < 4; e++) {
                int rj = pm0 + ms * 16 + g + ((e >> 1) << 3);
                int cm = pn0 + ns * 8 + tg * 2 + (e & 1);
                sm[C_PK + cm * STR_PK + rj] =
                    f2tf(fmaxf(DP[ms][ns][e], 0.f) * PHI_SCALE);
            }
    for (int idx = t; idx < DK * CHUNK; idx += 256) {
        int i = idx & 127, d = idx >> 7;
        sm[C_KQ + i * STR_KQ + d] = f2tf(queries[(h * DK + d) * NSEQ + nbase + i]);
    }
    __syncthreads();

    // d) GEMM phi_q (frags)
    #pragma unroll
    for (int ms = 0; ms < 2; ms++)
        #pragma unroll
        for (int ns = 0; ns < 8; ns++)
            #pragma unroll
            for (int e = 0; e < 4; e++) DP[ms][ns][e] = 0.f;
    for (int kk = 0; kk < 64; kk += 8) {
        uint32_t A[2][4], B[8][2];
        #pragma unroll
        for (int ms = 0; ms < 2; ms++) {
            int r0 = pm0 + ms * 16 + g;
            A[ms][0] = sm[C_KQ + r0 * STR_KQ + kk + tg];
            A[ms][1] = sm[C_KQ + (r0 + 8) * STR_KQ + kk + tg];
            A[ms][2] = sm[C_KQ + r0 * STR_KQ + kk + tg + 4];
            A[ms][3] = sm[C_KQ + (r0 + 8) * STR_KQ + kk + tg + 4];
        }
        #pragma unroll
        for (int ns = 0; ns < 8; ns++) {
            B[ns][0] = sm[C_F + (kk + tg) * STR_F + pn0 + ns * 8 + g];
            B[ns][1] = sm[C_F + (kk + tg + 4) * STR_F + pn0 + ns * 8 + g];
        }
        #pragma unroll
        for (int ms = 0; ms < 2; ms++)
            #pragma unroll
            for (int ns = 0; ns < 8; ns++) mma8(DP[ms][ns], A[ms], B[ns]);
    }
    __syncthreads();   // all reads of Q/F done -> C_KQ/C_F reusable

    // e) epilogue phi_q -> sPQ[i][m]; stage St+ (prefix [S|z]) and V+
    #pragma unroll
    for (int ms = 0; ms < 2; ms++)
        #pragma unroll
        for (int ns = 0; ns < 8; ns++)
            #pragma unroll
            for (int e = 0; e < 4; e++) {
                int ri = pm0 + ms * 16 + g + ((e >> 1) << 3);
                int cm = pn0 + ns * 8 + tg * 2 + (e & 1);
                sm[C_PQ + ri * STR_PQ + cm] =
                    f2tf(fmaxf(DP[ms][ns][e], 0.f) * PHI_SCALE);
            }
    {
        const float* Sg = g_S + (size_t)(h * NC + c) * MF * VP;
        for (int idx = t; idx < MF * VP; idx += 256)
            sm[C_ST + idx] = f2tf(Sg[idx]);          // [m][v], stride 72 native
        for (int idx = t; idx < DVV * CHUNK; idx += 256) {
            int j = idx & 127, v = idx >> 7;
            sm[C_V + j * STR_V + v] = f2tf(values[(h * DVV + v) * NSEQ + nbase + j]);
        }
        for (int idx = t; idx < CHUNK * 8; idx += 256) {
            int j = idx >> 3, v = 64 + (idx & 7);
            sm[C_V + j * STR_V + v] = (v == 64) ? 0x3F800000u : 0u;
        }
    }
    __syncthreads();

    // f) GEMM scores: A=sPQ, B=sPK, K=128 (frags in DP).
    // Causal skip: warps whose whole 32x64 tile lies above the diagonal
    // (pn0 > pm0 + 31, i.e. warps 4 and 5) do no MMAs — DP stays 0, and the
    // mask epilogue writes the identical zeros.
    #pragma unroll
    for (int ms = 0; ms < 2; ms++)
        #pragma unroll
        for (int ns = 0; ns < 8; ns++)
            #pragma unroll
            for (int e = 0; e < 4; e++) DP[ms][ns][e] = 0.f;
    if (pn0 <= pm0 + 31) {
        for (int kk = 0; kk < CHUNK; kk += 8) {
            uint32_t A[2][4], B[8][2];
            #pragma unroll
            for (int ms = 0; ms < 2; ms++) {
                int r0 = pm0 + ms * 16 + g;
                A[ms][0] = sm[C_PQ + r0 * STR_PQ + kk + tg];
                A[ms][1] = sm[C_PQ + (r0 + 8) * STR_PQ + kk + tg];
                A[ms][2] = sm[C_PQ + r0 * STR_PQ + kk + tg + 4];
                A[ms][3] = sm[C_PQ + (r0 + 8) * STR_PQ + kk + tg + 4];
            }
            #pragma unroll
            for (int ns = 0; ns < 8; ns++) {
                B[ns][0] = sm[C_PK + (kk + tg) * STR_PK + pn0 + ns * 8 + g];
                B[ns][1] = sm[C_PK + (kk + tg + 4) * STR_PK + pn0 + ns * 8 + g];
            }
            #pragma unroll
            for (int ms = 0; ms < 2; ms++)
                #pragma unroll
                for (int ns = 0; ns < 8; ns++) mma8(DP[ms][ns], A[ms], B[ns]);
        }
    }
    __syncthreads();   // all reads of sPK done

    // g) epilogue scores: causal mask -> sSc[i][j] (overwrites C_PK region)
    #pragma unroll
    for (int ms = 0; ms < 2; ms++)
        #pragma unroll
        for (int ns = 0; ns < 8; ns++)
            #pragma unroll
            for (int e = 0; e < 4; e++) {
                int ri = pm0 + ms * 16 + g + ((e >> 1) << 3);
                int cj = pn0 + ns * 8 + tg * 2 + (e & 1);
                float s = (cj <= ri) ? DP[ms][ns][e] : 0.f;
                sm[C_PK + ri * STR_SC + cj] = f2tf(s);
            }
    __syncthreads();

    // h) GEMM out: [out|norm][i][v+] = phiQ.St+ + Sc.V+ ; warp tile 16x72
    {
        const int i0 = w * 16;
        float D[9][4] = {};
        for (int kk = 0; kk < CHUNK; kk += 8) {       // pass 1: phiQ . St+
            uint32_t A[4];
            A[0] = sm[C_PQ + (i0 + g) * STR_PQ + kk + tg];
            A[1] = sm[C_PQ + (i0 + g + 8) * STR_PQ + kk + tg];
            A[2] = sm[C_PQ + (i0 + g) * STR_PQ + kk + tg + 4];
            A[3] = sm[C_PQ + (i0 + g + 8) * STR_PQ + kk + tg + 4];
            #pragma unroll
            for (int ns = 0; ns < 9; ns++) {
                uint32_t B[2];
                B[0] = sm[C_ST + (kk + tg) * STR_ST + ns * 8 + g];
                B[1] = sm[C_ST + (kk + tg + 4) * STR_ST + ns * 8 + g];
                mma8(D[ns], A, B);
            }
        }
        // pass 2: Sc . V+, k-loop truncated at the diagonal — Sc[i][j] = 0 for
        // j > i, and rows of this warp end at i0+15, so only (i0+16)/8 k-steps
        // contribute nonzero terms.
        const int kend = i0 + 16;
        for (int kk = 0; kk < kend; kk += 8) {
            uint32_t A[4];
            A[0] = sm[C_PK + (i0 + g) * STR_SC + kk + tg];
            A[1] = sm[C_PK + (i0 + g + 8) * STR_SC + kk + tg];
            A[2] = sm[C_PK + (i0 + g) * STR_SC + kk + tg + 4];
            A[3] = sm[C_PK + (i0 + g + 8) * STR_SC + kk + tg + 4];
            #pragma unroll
            for (int ns = 0; ns < 9; ns++) {
                uint32_t B[2];
                B[0] = sm[C_V + (kk + tg) * STR_V + ns * 8 + g];
                B[1] = sm[C_V + (kk + tg + 4) * STR_V + ns * 8 + g];
                mma8(D[ns], A, B);
            }
        }
        // i) norm = column 64 (ns=8, tg=0, e=0/2) -> broadcast within row group
        float nlo = __shfl_sync(0xffffffffu, D[8][0], lane & 28);
        float nhi = __shfl_sync(0xffffffffu, D[8][2], lane & 28);
        float ilo = 1.f / nlo, ihi = 1.f / nhi;
        #pragma unroll
        for (int ns = 0; ns < 8; ns++)
            #pragma unroll
            for (int e = 0; e < 4; e++) {
                int ri = i0 + g + ((e >> 1) << 3);
                int v  = ns * 8 + tg * 2 + (e & 1);
                out[(h * DVV + v) * NSEQ + nbase + ri] =
                    D[ns][e] * ((e >> 1) ? ihi : ilo);
            }
    }
}

// ===========================================================================
extern "C" void kernel_launch(void* const* d_in, const int* in_sizes, int n_in,
                              void* d_out, int out_size)
{
    const float* keys    = (const float*)d_in[0];
    const float* values  = (const float*)d_in[1];
    const float* queries = (const float*)d_in[2];
    const float* feat    = (const float*)d_in[3];
    float* out = (float*)d_out;

    cudaFuncSetAttribute(kA, cudaFuncAttributeMaxDynamicSharedMemorySize, A_SMB);
    cudaFuncSetAttribute(kC, cudaFuncAttributeMaxDynamicSharedMemorySize, C_SMB);

    kA<<<dim3(NC, BH), 256, A_SMB>>>(keys, values, feat);
    kB<<<dim3(BH, 36), 256>>>();
    kC<<<dim3(NC, BH), 256, C_SMB>>>(queries, keys, values, feat, out);
}